// round 4
// baseline (speedup 1.0000x reference)
#include <cuda_runtime.h>
#include <cuda_bf16.h>
#include <mma.h>
#include <cstdint>

using namespace nvcuda;

// ESSAttn: b=8, C=64, H=W=256, N=65536
// Layouts: x, scratch (q2n,k2d,v), out are [b][C][N]  (b<<22 | c<<16 | n)

#define NPIX 65536
#define CHN  64
#define NBAT 8

// ---------------- scratch (device globals; allocation-free) ----------------
__device__ float g_q2n[(size_t)NBAT * CHN * NPIX];
__device__ float g_k2d[(size_t)NBAT * CHN * NPIX];
__device__ float g_v  [(size_t)NBAT * CHN * NPIX];
__device__ float g_M  [NBAT * CHN * CHN];
__device__ float g_css[NBAT * CHN];
// weights pre-split to bf16 hi/lo; row-major [out_ch][in_ch] == col-major matrix_b (ld=64)
__device__ __nv_bfloat16 g_wqhi[192 * 64], g_wqlo[192 * 64];
__device__ __nv_bfloat16 g_wlhi[64 * 64],  g_wllo[64 * 64];
__device__ __nv_bfloat16 g_kvThi[NBAT * 64 * 64], g_kvTlo[NBAT * 64 * 64];

// ---------------------------------------------------------------------------
// prep: split weights to bf16 hi/lo, zero accumulators
__global__ void essa_prep(const float* __restrict__ wqkv, const float* __restrict__ wln) {
    int i = blockIdx.x * 256 + threadIdx.x;   // grid 128 -> 32768
    if (i < 12288) {
        float v = wqkv[i];
        __nv_bfloat16 h = __float2bfloat16(v);
        g_wqhi[i] = h;
        g_wqlo[i] = __float2bfloat16(v - __bfloat162float(h));
    }
    if (i < 4096) {
        float v = wln[i];
        __nv_bfloat16 h = __float2bfloat16(v);
        g_wlhi[i] = h;
        g_wllo[i] = __float2bfloat16(v - __bfloat162float(h));
    }
    if (i < NBAT * CHN * CHN) g_M[i] = 0.f;
    if (i < NBAT * CHN)       g_css[i] = 0.f;
}

// ---------------------------------------------------------------------------
// qkv: per CTA 64 pixels, D[64,192] = x_tile @ Wqkv^T via split-bf16 wmma.
// All fragments from SMEM. Phase 1: hh + lh (B=Bhi). Phase 2: hl (B=Blo).
// smem: [0,8K) Ah | [8K,16K) Al | [16K,40K) B | C(48K floats) overlaps all.
__global__ __launch_bounds__(128) void essa_qkv_tc(const float* __restrict__ x,
                                                   const float* __restrict__ bqkv) {
    __shared__ __align__(16) char sm[49152];
    __nv_bfloat16* Ah = reinterpret_cast<__nv_bfloat16*>(sm);
    __nv_bfloat16* Al = reinterpret_cast<__nv_bfloat16*>(sm + 8192);
    __nv_bfloat16* Bs = reinterpret_cast<__nv_bfloat16*>(sm + 16384);
    float* C = reinterpret_cast<float*>(sm);

    const int tid = threadIdx.x;
    const int wid = tid >> 5;
    const int b = blockIdx.y;
    const int n0 = blockIdx.x << 6;
    const size_t base = (size_t)b << 22;

    // ---- load x tile (split) + Bhi ----
    {
        const int p = tid & 63, kh = (tid >> 6) << 5;
        const int n = n0 + p;
#pragma unroll 8
        for (int i = 0; i < 32; ++i) {
            int k = kh + i;
            float v = x[base + ((size_t)k << 16) + n];
            __nv_bfloat16 h = __float2bfloat16(v);
            Ah[k * 64 + p] = h;
            Al[k * 64 + p] = __float2bfloat16(v - __bfloat162float(h));
        }
        const float4* src = reinterpret_cast<const float4*>(g_wqhi);
        float4* dst = reinterpret_cast<float4*>(Bs);
#pragma unroll
        for (int i = tid; i < 1536; i += 128) dst[i] = src[i];
    }
    __syncthreads();

    wmma::fragment<wmma::accumulator, 16, 16, 16, float> acc[4][3];
#pragma unroll
    for (int mt = 0; mt < 4; ++mt)
#pragma unroll
        for (int j = 0; j < 3; ++j) wmma::fill_fragment(acc[mt][j], 0.f);

    const int nt0 = wid * 3;

    // ---- phase 1: Ah*Bh + Al*Bh ----
#pragma unroll
    for (int ks = 0; ks < 4; ++ks) {
        wmma::fragment<wmma::matrix_b, 16, 16, 16, __nv_bfloat16, wmma::col_major> bf[3];
#pragma unroll
        for (int j = 0; j < 3; ++j)
            wmma::load_matrix_sync(bf[j], Bs + (nt0 + j) * 1024 + ks * 16, 64);
#pragma unroll
        for (int mt = 0; mt < 4; ++mt) {
            wmma::fragment<wmma::matrix_a, 16, 16, 16, __nv_bfloat16, wmma::col_major> afh, afl;
            wmma::load_matrix_sync(afh, Ah + ks * 1024 + mt * 16, 64);
            wmma::load_matrix_sync(afl, Al + ks * 1024 + mt * 16, 64);
#pragma unroll
            for (int j = 0; j < 3; ++j) wmma::mma_sync(acc[mt][j], afh, bf[j], acc[mt][j]);
#pragma unroll
            for (int j = 0; j < 3; ++j) wmma::mma_sync(acc[mt][j], afl, bf[j], acc[mt][j]);
        }
    }
    __syncthreads();
    // ---- swap in Blo ----
    {
        const float4* src = reinterpret_cast<const float4*>(g_wqlo);
        float4* dst = reinterpret_cast<float4*>(Bs);
#pragma unroll
        for (int i = tid; i < 1536; i += 128) dst[i] = src[i];
    }
    __syncthreads();
    // ---- phase 2: Ah*Bl ----
#pragma unroll
    for (int ks = 0; ks < 4; ++ks) {
        wmma::fragment<wmma::matrix_b, 16, 16, 16, __nv_bfloat16, wmma::col_major> bf[3];
#pragma unroll
        for (int j = 0; j < 3; ++j)
            wmma::load_matrix_sync(bf[j], Bs + (nt0 + j) * 1024 + ks * 16, 64);
#pragma unroll
        for (int mt = 0; mt < 4; ++mt) {
            wmma::fragment<wmma::matrix_a, 16, 16, 16, __nv_bfloat16, wmma::col_major> afh;
            wmma::load_matrix_sync(afh, Ah + ks * 1024 + mt * 16, 64);
#pragma unroll
            for (int j = 0; j < 3; ++j) wmma::mma_sync(acc[mt][j], afh, bf[j], acc[mt][j]);
        }
    }
    __syncthreads();   // A, B dead; C takes the whole region
#pragma unroll
    for (int mt = 0; mt < 4; ++mt)
#pragma unroll
        for (int j = 0; j < 3; ++j)
            wmma::store_matrix_sync(C + (nt0 + j) * 1024 + mt * 16, acc[mt][j],
                                    64, wmma::mem_col_major);
    __syncthreads();

    // ---- epilogues (C col-major: C[ch*64 + pixel], conflict-free) ----
    if (tid < 64) {
        const int p = tid, n = n0 + p;
        float qv[64];
#pragma unroll 8
        for (int j = 0; j < 64; ++j) qv[j] = C[j * 64 + p] + bqkv[j];
        float mean = 0.f;
#pragma unroll 8
        for (int j = 0; j < 64; ++j) mean += qv[j];
        mean *= (1.f / 64.f);
        float ss = 0.f;
#pragma unroll 8
        for (int j = 0; j < 64; ++j) { float t = qv[j] - mean; t = t * t; qv[j] = t; ss += t; }
        float inv = 1.f / (ss + 1e-7f);
        float nr = 0.f;
#pragma unroll 8
        for (int j = 0; j < 64; ++j) { float t = qv[j] * inv; nr = fmaf(t, t, nr); }
        float sc = inv / fmaxf(sqrtf(nr), 1e-12f);
#pragma unroll 8
        for (int j = 0; j < 64; ++j) g_q2n[base + ((size_t)j << 16) + n] = qv[j] * sc;
    } else {
        const int p = tid - 64, n = n0 + p;
        float kv[64];
#pragma unroll 8
        for (int j = 0; j < 64; ++j) kv[j] = C[(64 + j) * 64 + p] + bqkv[64 + j];
        float mean = 0.f;
#pragma unroll 8
        for (int j = 0; j < 64; ++j) mean += kv[j];
        mean *= (1.f / 64.f);
        float ss = 0.f;
#pragma unroll 8
        for (int j = 0; j < 64; ++j) { float t = kv[j] - mean; t = t * t; kv[j] = t; ss += t; }
        float inv = 1.f / (ss + 1e-7f);
#pragma unroll 8
        for (int j = 0; j < 64; ++j) g_k2d[base + ((size_t)j << 16) + n] = kv[j] * inv;
    }
    {
        const int p = tid & 63, jh = (tid >> 6) << 5;
        const int n = n0 + p;
#pragma unroll 8
        for (int i = 0; i < 32; ++i) {
            int j = jh + i;
            g_v[base + ((size_t)j << 16) + n] = C[(128 + j) * 64 + p] + bqkv[128 + j];
        }
    }
}

// ---------------------------------------------------------------------------
// Kernel M: M[c][d] += sum_n k2d[n][c]*v[n][d], plus column sumsq of k2d (fp32)
__global__ __launch_bounds__(256) void essa_kvacc() {
    const int b = blockIdx.y;
    const int n0 = blockIdx.x << 9;
    const size_t base = (size_t)b << 22;

    __shared__ float ks[64 * 33];
    __shared__ float vs[64 * 33];

    const int ty = threadIdx.x >> 4;
    const int tx = threadIdx.x & 15;

    float acc[4][4];
#pragma unroll
    for (int i = 0; i < 4; ++i)
#pragma unroll
        for (int j = 0; j < 4; ++j) acc[i][j] = 0.f;
    float cssr = 0.f;

    for (int t = 0; t < 16; ++t) {
        const int nb = n0 + (t << 5);
        __syncthreads();
        for (int i = threadIdx.x; i < 2048; i += 256) {
            int c = i >> 5, nn = i & 31;
            size_t g = base + ((size_t)c << 16) + nb + nn;
            ks[c * 33 + nn] = g_k2d[g];
            vs[c * 33 + nn] = g_v[g];
        }
        __syncthreads();
        const float* kp = ks + (ty << 2) * 33;
        const float* vp = vs + (tx << 2) * 33;
#pragma unroll 8
        for (int nn = 0; nn < 32; ++nn) {
            float k0 = kp[nn], k1 = kp[33 + nn], k2 = kp[66 + nn], k3 = kp[99 + nn];
            float v0 = vp[nn], v1 = vp[33 + nn], v2 = vp[66 + nn], v3 = vp[99 + nn];
            acc[0][0] = fmaf(k0, v0, acc[0][0]); acc[0][1] = fmaf(k0, v1, acc[0][1]);
            acc[0][2] = fmaf(k0, v2, acc[0][2]); acc[0][3] = fmaf(k0, v3, acc[0][3]);
            acc[1][0] = fmaf(k1, v0, acc[1][0]); acc[1][1] = fmaf(k1, v1, acc[1][1]);
            acc[1][2] = fmaf(k1, v2, acc[1][2]); acc[1][3] = fmaf(k1, v3, acc[1][3]);
            acc[2][0] = fmaf(k2, v0, acc[2][0]); acc[2][1] = fmaf(k2, v1, acc[2][1]);
            acc[2][2] = fmaf(k2, v2, acc[2][2]); acc[2][3] = fmaf(k2, v3, acc[2][3]);
            acc[3][0] = fmaf(k3, v0, acc[3][0]); acc[3][1] = fmaf(k3, v1, acc[3][1]);
            acc[3][2] = fmaf(k3, v2, acc[3][2]); acc[3][3] = fmaf(k3, v3, acc[3][3]);
        }
        if (threadIdx.x < 64) {
            const float* cp = ks + threadIdx.x * 33;
#pragma unroll 8
            for (int nn = 0; nn < 32; ++nn) { float u = cp[nn]; cssr = fmaf(u, u, cssr); }
        }
    }

    float* Mp = g_M + (b << 12);
#pragma unroll
    for (int i = 0; i < 4; ++i)
#pragma unroll
        for (int j = 0; j < 4; ++j)
            atomicAdd(&Mp[((ty << 2) + i) * 64 + (tx << 2) + j], acc[i][j]);
    if (threadIdx.x < 64) atomicAdd(&g_css[(b << 6) + threadIdx.x], cssr);
}

// ---------------------------------------------------------------------------
// kv[c][d] = M[c][d] / max(||k2d[:,c]||, 1e-12) -> transposed, split-bf16
__global__ void essa_kvfin() {
    int i = blockIdx.x * 256 + threadIdx.x;   // grid 128 -> 32768
    int b = i >> 12;
    int r = i & 4095;
    int c = r >> 6, d = r & 63;
    float nrm = fmaxf(sqrtf(g_css[(b << 6) + c]), 1e-12f);
    float v = g_M[i] / nrm;
    __nv_bfloat16 h = __float2bfloat16(v);
    int o = (b << 12) + (d << 6) + c;
    g_kvThi[o] = h;
    g_kvTlo[o] = __float2bfloat16(v - __bfloat162float(h));
}

// ---------------------------------------------------------------------------
// out: MMA1 t2 = q2n @ kvT^T (scaled 1/256), attn = v + t2,
// MMA2 out = attn @ wln^T + bln. All fragments from SMEM.
// smem: [0,8K)Ah |[8K,16K)Al |[16K,24K)B1h |[24K,32K)B1l |[32K,40K)B2h |[40K,48K)B2l
//       C (16KB floats) overlaps [16K,32K) after MMA1.
__global__ __launch_bounds__(128) void essa_out_tc(const float* __restrict__ bln,
                                                   float* __restrict__ out) {
    __shared__ __align__(16) char sm[49152];
    __nv_bfloat16* Ah  = reinterpret_cast<__nv_bfloat16*>(sm);
    __nv_bfloat16* Al  = reinterpret_cast<__nv_bfloat16*>(sm + 8192);
    __nv_bfloat16* B1h = reinterpret_cast<__nv_bfloat16*>(sm + 16384);
    __nv_bfloat16* B1l = reinterpret_cast<__nv_bfloat16*>(sm + 24576);
    __nv_bfloat16* B2h = reinterpret_cast<__nv_bfloat16*>(sm + 32768);
    __nv_bfloat16* B2l = reinterpret_cast<__nv_bfloat16*>(sm + 40960);
    float* C = reinterpret_cast<float*>(sm + 16384);

    const int tid = threadIdx.x;
    const int wid = tid >> 5;
    const int b = blockIdx.y;
    const int n0 = blockIdx.x << 6;
    const size_t base = (size_t)b << 22;

    // ---- load A (q2n split) + B1 (kvT) + B2 (wln) ----
    {
        const int p = tid & 63, kh = (tid >> 6) << 5;
        const int n = n0 + p;
#pragma unroll 8
        for (int i = 0; i < 32; ++i) {
            int k = kh + i;
            float v = g_q2n[base + ((size_t)k << 16) + n];
            __nv_bfloat16 h = __float2bfloat16(v);
            Ah[k * 64 + p] = h;
            Al[k * 64 + p] = __float2bfloat16(v - __bfloat162float(h));
        }
        const float4* s1h = reinterpret_cast<const float4*>(g_kvThi + (b << 12));
        const float4* s1l = reinterpret_cast<const float4*>(g_kvTlo + (b << 12));
        const float4* s2h = reinterpret_cast<const float4*>(g_wlhi);
        const float4* s2l = reinterpret_cast<const float4*>(g_wllo);
#pragma unroll
        for (int i = tid; i < 512; i += 128) {
            reinterpret_cast<float4*>(B1h)[i] = s1h[i];
            reinterpret_cast<float4*>(B1l)[i] = s1l[i];
            reinterpret_cast<float4*>(B2h)[i] = s2h[i];
            reinterpret_cast<float4*>(B2l)[i] = s2l[i];
        }
    }
    __syncthreads();

    wmma::fragment<wmma::accumulator, 16, 16, 16, float> acc[4];

    // ---- MMA1 ----
#pragma unroll
    for (int mt = 0; mt < 4; ++mt) wmma::fill_fragment(acc[mt], 0.f);
#pragma unroll
    for (int ks = 0; ks < 4; ++ks) {
        wmma::fragment<wmma::matrix_b, 16, 16, 16, __nv_bfloat16, wmma::col_major> bfh, bfl;
        wmma::load_matrix_sync(bfh, B1h + wid * 1024 + ks * 16, 64);
        wmma::load_matrix_sync(bfl, B1l + wid * 1024 + ks * 16, 64);
#pragma unroll
        for (int mt = 0; mt < 4; ++mt) {
            wmma::fragment<wmma::matrix_a, 16, 16, 16, __nv_bfloat16, wmma::col_major> afh, afl;
            wmma::load_matrix_sync(afh, Ah + ks * 1024 + mt * 16, 64);
            wmma::load_matrix_sync(afl, Al + ks * 1024 + mt * 16, 64);
            wmma::mma_sync(acc[mt], afh, bfh, acc[mt]);
            wmma::mma_sync(acc[mt], afl, bfh, acc[mt]);
            wmma::mma_sync(acc[mt], afh, bfl, acc[mt]);
        }
    }
    __syncthreads();   // B1 dead -> C region
#pragma unroll
    for (int mt = 0; mt < 4; ++mt)
        wmma::store_matrix_sync(C + wid * 1024 + mt * 16, acc[mt], 64, wmma::mem_col_major);
    __syncthreads();

    // ---- attn = v + t2/256; rewrite A (split) ----
    {
        const int p = tid & 63, jh = (tid >> 6) << 5;
        const int n = n0 + p;
#pragma unroll 8
        for (int i = 0; i < 32; ++i) {
            int j = jh + i;
            float at = fmaf(C[j * 64 + p], 1.f / 256.f, g_v[base + ((size_t)j << 16) + n]);
            __nv_bfloat16 h = __float2bfloat16(at);
            Ah[j * 64 + p] = h;
            Al[j * 64 + p] = __float2bfloat16(at - __bfloat162float(h));
        }
    }
    __syncthreads();

    // ---- MMA2 ----
#pragma unroll
    for (int mt = 0; mt < 4; ++mt) wmma::fill_fragment(acc[mt], 0.f);
#pragma unroll
    for (int ks = 0; ks < 4; ++ks) {
        wmma::fragment<wmma::matrix_b, 16, 16, 16, __nv_bfloat16, wmma::col_major> bfh, bfl;
        wmma::load_matrix_sync(bfh, B2h + wid * 1024 + ks * 16, 64);
        wmma::load_matrix_sync(bfl, B2l + wid * 1024 + ks * 16, 64);
#pragma unroll
        for (int mt = 0; mt < 4; ++mt) {
            wmma::fragment<wmma::matrix_a, 16, 16, 16, __nv_bfloat16, wmma::col_major> afh, afl;
            wmma::load_matrix_sync(afh, Ah + ks * 1024 + mt * 16, 64);
            wmma::load_matrix_sync(afl, Al + ks * 1024 + mt * 16, 64);
            wmma::mma_sync(acc[mt], afh, bfh, acc[mt]);
            wmma::mma_sync(acc[mt], afl, bfh, acc[mt]);
            wmma::mma_sync(acc[mt], afh, bfl, acc[mt]);
        }
    }
    __syncthreads();
#pragma unroll
    for (int mt = 0; mt < 4; ++mt)
        wmma::store_matrix_sync(C + wid * 1024 + mt * 16, acc[mt], 64, wmma::mem_col_major);
    __syncthreads();

    // ---- out = C + bias ----
    {
        const int p = tid & 63, jh = (tid >> 6) << 5;
        const int n = n0 + p;
#pragma unroll 8
        for (int i = 0; i < 32; ++i) {
            int j = jh + i;
            out[base + ((size_t)j << 16) + n] = C[j * 64 + p] + bln[j];
        }
    }
}

// ---------------------------------------------------------------------------
extern "C" void kernel_launch(void* const* d_in, const int* in_sizes, int n_in,
                              void* d_out, int out_size) {
    const float* x    = (const float*)d_in[0];
    const float* wqkv = (const float*)d_in[1];
    const float* bqkv = (const float*)d_in[2];
    const float* wln  = (const float*)d_in[3];
    const float* bln  = (const float*)d_in[4];
    float* out = (float*)d_out;

    essa_prep<<<128, 256>>>(wqkv, wln);

    dim3 gridT(NPIX / 64, NBAT);
    essa_qkv_tc<<<gridT, 128>>>(x, bqkv);

    dim3 gridM(NPIX / 512, NBAT);
    essa_kvacc<<<gridM, 256>>>();

    essa_kvfin<<<128, 256>>>();

    essa_out_tc<<<gridT, 128>>>(bln, out);
}

// round 6
// speedup vs baseline: 1.0435x; 1.0435x over previous
#include <cuda_runtime.h>
#include <cstdint>

// ESSAttn: b=8, C=64, H=W=256, N=65536
// x, out: [b][C][N]  (b<<22 | c<<16 | n)
// scratch q2n,k2d,v: [b][N][C]  (b<<22 | n<<6 | c)

#define NPIX 65536
#define CHN  64
#define NBAT 8

typedef unsigned long long u64;

// ---------------- scratch ----------------
__device__ float g_q2n[(size_t)NBAT * CHN * NPIX];
__device__ float g_k2d[(size_t)NBAT * CHN * NPIX];
__device__ float g_v  [(size_t)NBAT * CHN * NPIX];
__device__ float g_M  [NBAT * CHN * CHN];
__device__ float g_css[NBAT * CHN];
__device__ float g_kvT[NBAT * CHN * CHN];   // [b][d][c]

// ---------------- packed fp32 helpers ----------------
__device__ __forceinline__ u64 ffma2(u64 a, u64 b, u64 c) {
    u64 d;
    asm("fma.rn.f32x2 %0, %1, %2, %3;" : "=l"(d) : "l"(a), "l"(b), "l"(c));
    return d;
}
__device__ __forceinline__ u64 fadd2(u64 a, u64 b) {
    u64 d;
    asm("add.rn.f32x2 %0, %1, %2;" : "=l"(d) : "l"(a), "l"(b));
    return d;
}
__device__ __forceinline__ u64 pack2(float lo, float hi) {
    u64 d;
    asm("mov.b64 %0, {%1, %2};" : "=l"(d) : "f"(lo), "f"(hi));
    return d;
}
__device__ __forceinline__ float2 unpack2(u64 v) {
    float lo, hi;
    asm("mov.b64 {%0, %1}, %2;" : "=f"(lo), "=f"(hi) : "l"(v));
    return make_float2(lo, hi);
}
__device__ __forceinline__ float hsum2(u64 a, u64 b) {
    float2 r = unpack2(fadd2(a, b));
    return r.x + r.y;
}

// 64-wide packed dot: row[j] = xp . W[j0+j] + bias   (full K=64: 32 packed pairs)
__device__ __forceinline__ void gemm_seg(const u64* __restrict__ xp,
                                         const float* __restrict__ sW,
                                         const float* __restrict__ sB,
                                         float* __restrict__ row, int j0) {
#pragma unroll 4
    for (int j = 0; j < 64; ++j) {
        const ulonglong2* wp = reinterpret_cast<const ulonglong2*>(sW + (j0 + j) * 64);
        u64 s0 = 0, s1 = 0, s2 = 0, s3 = 0;
#pragma unroll
        for (int t = 0; t < 8; ++t) {
            ulonglong2 wa = wp[2 * t], wb = wp[2 * t + 1];
            s0 = ffma2(xp[4 * t + 0], wa.x, s0);
            s1 = ffma2(xp[4 * t + 1], wa.y, s1);
            s2 = ffma2(xp[4 * t + 2], wb.x, s2);
            s3 = ffma2(xp[4 * t + 3], wb.y, s3);
        }
        row[j] = hsum2(fadd2(s0, s1), fadd2(s2, s3)) + sB[j0 + j];
    }
}

// ---------------------------------------------------------------------------
// qkv: 128 pixels/CTA. 192 packed dots per pixel + stats. Also zeros accums.
__global__ __launch_bounds__(128) void essa_qkv(const float* __restrict__ x,
                                                const float* __restrict__ wqkv,
                                                const float* __restrict__ bqkv) {
    extern __shared__ float sW[];        // 12288 W + 192 bias
    float* sB = sW + 12288;

    const int tid = threadIdx.x;
    const int b = blockIdx.y;
    const int n = (blockIdx.x << 7) + tid;
    const size_t basecn = (size_t)b << 22;
    const size_t rownc = basecn + ((size_t)n << 6);

    if (blockIdx.x == 0 && b == 0) {     // runs before kvacc launch
        for (int i = tid; i < NBAT * CHN * CHN; i += 128) g_M[i] = 0.f;
        for (int i = tid; i < NBAT * CHN; i += 128) g_css[i] = 0.f;
    }

    for (int i = tid; i < 3072; i += 128)
        reinterpret_cast<float4*>(sW)[i] = reinterpret_cast<const float4*>(wqkv)[i];
    for (int i = tid; i < 192; i += 128) sB[i] = bqkv[i];
    __syncthreads();

    u64 xp[32];
#pragma unroll
    for (int c = 0; c < 32; ++c)
        xp[c] = pack2(x[basecn + ((size_t)(2 * c) << 16) + n],
                      x[basecn + ((size_t)(2 * c + 1) << 16) + n]);

    float row[64];

    // ---- Q ----
    gemm_seg(xp, sW, sB, row, 0);
    {
        float mean = 0.f;
#pragma unroll 8
        for (int j = 0; j < 64; ++j) mean += row[j];
        mean *= (1.f / 64.f);
        float ss = 0.f;
#pragma unroll 8
        for (int j = 0; j < 64; ++j) { float t = row[j] - mean; t = t * t; row[j] = t; ss += t; }
        float inv = 1.f / (ss + 1e-7f);
        float nr = 0.f;
#pragma unroll 8
        for (int j = 0; j < 64; ++j) { float t = row[j] * inv; nr = fmaf(t, t, nr); }
        float sc = inv / fmaxf(sqrtf(nr), 1e-12f);
        float4* dq = reinterpret_cast<float4*>(g_q2n + rownc);
#pragma unroll
        for (int t = 0; t < 16; ++t)
            dq[t] = make_float4(row[4 * t] * sc, row[4 * t + 1] * sc,
                                row[4 * t + 2] * sc, row[4 * t + 3] * sc);
    }
    // ---- K ----
    gemm_seg(xp, sW, sB, row, 64);
    {
        float mean = 0.f;
#pragma unroll 8
        for (int j = 0; j < 64; ++j) mean += row[j];
        mean *= (1.f / 64.f);
        float ss = 0.f;
#pragma unroll 8
        for (int j = 0; j < 64; ++j) { float t = row[j] - mean; t = t * t; row[j] = t; ss += t; }
        float inv = 1.f / (ss + 1e-7f);
        float4* dk = reinterpret_cast<float4*>(g_k2d + rownc);
#pragma unroll
        for (int t = 0; t < 16; ++t)
            dk[t] = make_float4(row[4 * t] * inv, row[4 * t + 1] * inv,
                                row[4 * t + 2] * inv, row[4 * t + 3] * inv);
    }
    // ---- V ----
    gemm_seg(xp, sW, sB, row, 128);
    {
        float4* dv = reinterpret_cast<float4*>(g_v + rownc);
#pragma unroll
        for (int t = 0; t < 16; ++t)
            dv[t] = make_float4(row[4 * t], row[4 * t + 1], row[4 * t + 2], row[4 * t + 3]);
    }
}

// ---------------------------------------------------------------------------
// kvacc: M[c][d] += sum_n k2d[n][c]*v[n][d]; css[c] += sum k2d^2. Packed v side.
__global__ __launch_bounds__(256) void essa_kvacc() {
    const int b = blockIdx.y;
    const int n0 = blockIdx.x << 9;
    const size_t base = (size_t)b << 22;

    __shared__ float ks[64 * 33];        // [c][nn]
    __shared__ __align__(16) float vs[32 * 68];   // [nn][d]

    const int tid = threadIdx.x;
    const int ty = tid >> 4, tx = tid & 15;
    const int c0 = ty << 2, d0 = tx << 2;

    u64 acc[4][2];
#pragma unroll
    for (int i = 0; i < 4; ++i) { acc[i][0] = 0; acc[i][1] = 0; }
    float cssr = 0.f;

    for (int t = 0; t < 16; ++t) {
        const int nb = n0 + (t << 5);
        __syncthreads();
        for (int i = tid; i < 512; i += 256) {
            int nn = i >> 4, c4 = (i & 15) << 2;
            size_t g = base + ((size_t)(nb + nn) << 6) + c4;
            float4 kk = *reinterpret_cast<const float4*>(g_k2d + g);
            float4 vv = *reinterpret_cast<const float4*>(g_v + g);
            ks[(c4 + 0) * 33 + nn] = kk.x;
            ks[(c4 + 1) * 33 + nn] = kk.y;
            ks[(c4 + 2) * 33 + nn] = kk.z;
            ks[(c4 + 3) * 33 + nn] = kk.w;
            *reinterpret_cast<float4*>(vs + nn * 68 + c4) = vv;
        }
        __syncthreads();
        const float* kp = ks + c0 * 33;
#pragma unroll 4
        for (int nn = 0; nn < 32; ++nn) {
            ulonglong2 v01 = *reinterpret_cast<const ulonglong2*>(vs + nn * 68 + d0);
            float k0 = kp[nn], k1 = kp[33 + nn], k2 = kp[66 + nn], k3 = kp[99 + nn];
            u64 kk0 = pack2(k0, k0), kk1 = pack2(k1, k1);
            u64 kk2 = pack2(k2, k2), kk3 = pack2(k3, k3);
            acc[0][0] = ffma2(kk0, v01.x, acc[0][0]); acc[0][1] = ffma2(kk0, v01.y, acc[0][1]);
            acc[1][0] = ffma2(kk1, v01.x, acc[1][0]); acc[1][1] = ffma2(kk1, v01.y, acc[1][1]);
            acc[2][0] = ffma2(kk2, v01.x, acc[2][0]); acc[2][1] = ffma2(kk2, v01.y, acc[2][1]);
            acc[3][0] = ffma2(kk3, v01.x, acc[3][0]); acc[3][1] = ffma2(kk3, v01.y, acc[3][1]);
        }
        if (tid < 64) {
            const float* cp = ks + tid * 33;
#pragma unroll 8
            for (int nn = 0; nn < 32; ++nn) { float u = cp[nn]; cssr = fmaf(u, u, cssr); }
        }
    }

    float* Mp = g_M + (b << 12);
#pragma unroll
    for (int i = 0; i < 4; ++i) {
        float2 a0 = unpack2(acc[i][0]), a1 = unpack2(acc[i][1]);
        atomicAdd(&Mp[(c0 + i) * 64 + d0 + 0], a0.x);
        atomicAdd(&Mp[(c0 + i) * 64 + d0 + 1], a0.y);
        atomicAdd(&Mp[(c0 + i) * 64 + d0 + 2], a1.x);
        atomicAdd(&Mp[(c0 + i) * 64 + d0 + 3], a1.y);
    }
    if (tid < 64) atomicAdd(&g_css[(b << 6) + tid], cssr);
}

// ---------------------------------------------------------------------------
// kvfin: kvT[b][d][c] = M[b][c][d] / max(||k2d[:,c]||, 1e-12)
__global__ void essa_kvfin() {
    int i = blockIdx.x * 256 + threadIdx.x;   // grid 128 -> 32768
    int b = i >> 12;
    int r = i & 4095;
    int c = r >> 6, d = r & 63;
    float nrm = fmaxf(sqrtf(g_css[(b << 6) + c]), 1e-12f);
    g_kvT[(b << 12) + (d << 6) + c] = g_M[i] / nrm;
}

// ---------------------------------------------------------------------------
// out: t2 = q2n @ kvT^T /256, attn = v + t2, out = attn @ wln^T + bln
__global__ __launch_bounds__(128) void essa_out(const float* __restrict__ wln,
                                                const float* __restrict__ bln,
                                                float* __restrict__ out) {
    __shared__ __align__(16) float sKV[4096];   // [d][c]
    __shared__ __align__(16) float sWl[4096];   // [d][c]
    __shared__ float sBl[64];

    const int tid = threadIdx.x;
    const int b = blockIdx.y;
    const int n = (blockIdx.x << 7) + tid;
    const size_t basecn = (size_t)b << 22;
    const size_t rownc = basecn + ((size_t)n << 6);

    for (int i = tid; i < 1024; i += 128) {
        reinterpret_cast<float4*>(sKV)[i] =
            reinterpret_cast<const float4*>(g_kvT + (b << 12))[i];
        reinterpret_cast<float4*>(sWl)[i] = reinterpret_cast<const float4*>(wln)[i];
    }
    if (tid < 64) sBl[tid] = bln[tid];
    __syncthreads();

    u64 xp[32];
    {
        const ulonglong2* q2 = reinterpret_cast<const ulonglong2*>(g_q2n + rownc);
#pragma unroll
        for (int t = 0; t < 16; ++t) { ulonglong2 w = q2[t]; xp[2 * t] = w.x; xp[2 * t + 1] = w.y; }
    }

    u64 ap[32];
    const float2* vrow = reinterpret_cast<const float2*>(g_v + rownc);
#pragma unroll 2
    for (int dp = 0; dp < 32; ++dp) {
        const ulonglong2* ka = reinterpret_cast<const ulonglong2*>(sKV + (2 * dp) * 64);
        const ulonglong2* kb = reinterpret_cast<const ulonglong2*>(sKV + (2 * dp + 1) * 64);
        u64 s0 = 0, s1 = 0, s2 = 0, s3 = 0;
#pragma unroll
        for (int t = 0; t < 16; ++t) {        // full K=64: 32 pairs per row
            ulonglong2 wa = ka[t], wb = kb[t];
            s0 = ffma2(xp[2 * t],     wa.x, s0);
            s1 = ffma2(xp[2 * t + 1], wa.y, s1);
            s2 = ffma2(xp[2 * t],     wb.x, s2);
            s3 = ffma2(xp[2 * t + 1], wb.y, s3);
        }
        float ta = hsum2(s0, s1), tb = hsum2(s2, s3);
        float2 vv = vrow[dp];
        ap[dp] = pack2(fmaf(ta, 1.f / 256.f, vv.x), fmaf(tb, 1.f / 256.f, vv.y));
    }

#pragma unroll 4
    for (int j = 0; j < 64; ++j) {
        const ulonglong2* wp = reinterpret_cast<const ulonglong2*>(sWl + j * 64);
        u64 s0 = 0, s1 = 0, s2 = 0, s3 = 0;
#pragma unroll
        for (int t = 0; t < 8; ++t) {          // full K=64
            ulonglong2 wa = wp[2 * t], wb = wp[2 * t + 1];
            s0 = ffma2(ap[4 * t + 0], wa.x, s0);
            s1 = ffma2(ap[4 * t + 1], wa.y, s1);
            s2 = ffma2(ap[4 * t + 2], wb.x, s2);
            s3 = ffma2(ap[4 * t + 3], wb.y, s3);
        }
        out[basecn + ((size_t)j << 16) + n] = hsum2(fadd2(s0, s1), fadd2(s2, s3)) + sBl[j];
    }
}

// ---------------------------------------------------------------------------
extern "C" void kernel_launch(void* const* d_in, const int* in_sizes, int n_in,
                              void* d_out, int out_size) {
    const float* x    = (const float*)d_in[0];
    const float* wqkv = (const float*)d_in[1];
    const float* bqkv = (const float*)d_in[2];
    const float* wln  = (const float*)d_in[3];
    const float* bln  = (const float*)d_in[4];
    float* out = (float*)d_out;

    cudaFuncSetAttribute(essa_qkv, cudaFuncAttributeMaxDynamicSharedMemorySize, 49920);

    dim3 gridQ(NPIX / 128, NBAT);
    essa_qkv<<<gridQ, 128, 49920>>>(x, wqkv, bqkv);

    dim3 gridM(NPIX / 512, NBAT);
    essa_kvacc<<<gridM, 256>>>();

    essa_kvfin<<<128, 256>>>();

    essa_out<<<gridQ, 128>>>(wln, bln, out);
}